// round 2
// baseline (speedup 1.0000x reference)
#include <cuda_runtime.h>

#define HID   1024
#define NSEQ  1024
#define DHEAD 64

// scratch (static device arrays; no allocation)
__device__ float g_q[NSEQ * HID];
__device__ float g_k[NSEQ * HID];
__device__ float g_v[NSEQ * HID];
__device__ float g_pk[2048 * HID];
__device__ float g_pq[2048 * HID];
__device__ float g_scores[16 * NSEQ * NSEQ];
__device__ float g_rmax[16 * NSEQ];
__device__ float g_rinv[16 * NSEQ];
__device__ float g_ctx[NSEQ * HID];
__device__ float g_proj[NSEQ * HID];

// C[m][n] = sum_k A[m][k]*W[n][k] + bias[n].  128x128 tile, BK=8, 256 thr,
// 8x8/thread in split 4+4 fragments (rows ty*4 & 64+ty*4; cols tx*4 & 64+tx*4).
__global__ __launch_bounds__(256, 2)
void gemm_nt(const float* __restrict__ A,
             const float* __restrict__ W0, const float* __restrict__ b0, float* __restrict__ C0,
             const float* __restrict__ W1, const float* __restrict__ b1, float* __restrict__ C1,
             const float* __restrict__ W2, const float* __restrict__ b2, float* __restrict__ C2)
{
    const int z = blockIdx.z;
    const float* W    = (z == 0) ? W0 : ((z == 1) ? W1 : W2);
    const float* bias = (z == 0) ? b0 : ((z == 1) ? b1 : b2);
    float*       C    = (z == 0) ? C0 : ((z == 1) ? C1 : C2);

    __shared__ float As[2][8][128];
    __shared__ float Ws[2][8][128];

    const int m0 = blockIdx.y * 128, n0 = blockIdx.x * 128;
    const int t = threadIdx.x, tx = t & 15, ty = t >> 4;
    const int lrow = t >> 1, lk = (t & 1) * 4;
    const float* Ap = A + (size_t)(m0 + lrow) * HID + lk;
    const float* Wp = W + (size_t)(n0 + lrow) * HID + lk;

    { float4 a = *(const float4*)Ap, w = *(const float4*)Wp;
      As[0][lk+0][lrow]=a.x; As[0][lk+1][lrow]=a.y; As[0][lk+2][lrow]=a.z; As[0][lk+3][lrow]=a.w;
      Ws[0][lk+0][lrow]=w.x; Ws[0][lk+1][lrow]=w.y; Ws[0][lk+2][lrow]=w.z; Ws[0][lk+3][lrow]=w.w; }
    __syncthreads();

    float acc[8][8];
#pragma unroll
    for (int r = 0; r < 8; r++)
#pragma unroll
        for (int c = 0; c < 8; c++) acc[r][c] = 0.0f;

    const int NT = HID / 8;
    for (int kt = 0; kt < NT; kt++) {
        const int cur = kt & 1;
        float4 na, nw;
        if (kt + 1 < NT) { na = *(const float4*)(Ap + (kt+1)*8); nw = *(const float4*)(Wp + (kt+1)*8); }
#pragma unroll
        for (int k = 0; k < 8; k++) {
            float4 a0 = *(const float4*)&As[cur][k][ty*4];
            float4 a1 = *(const float4*)&As[cur][k][64 + ty*4];
            float4 w0 = *(const float4*)&Ws[cur][k][tx*4];
            float4 w1 = *(const float4*)&Ws[cur][k][64 + tx*4];
            float ar[8] = {a0.x,a0.y,a0.z,a0.w, a1.x,a1.y,a1.z,a1.w};
            float wr[8] = {w0.x,w0.y,w0.z,w0.w, w1.x,w1.y,w1.z,w1.w};
#pragma unroll
            for (int r = 0; r < 8; r++)
#pragma unroll
                for (int c = 0; c < 8; c++) acc[r][c] = fmaf(ar[r], wr[c], acc[r][c]);
        }
        if (kt + 1 < NT) {
            const int nx = cur ^ 1;
            As[nx][lk+0][lrow]=na.x; As[nx][lk+1][lrow]=na.y; As[nx][lk+2][lrow]=na.z; As[nx][lk+3][lrow]=na.w;
            Ws[nx][lk+0][lrow]=nw.x; Ws[nx][lk+1][lrow]=nw.y; Ws[nx][lk+2][lrow]=nw.z; Ws[nx][lk+3][lrow]=nw.w;
            __syncthreads();
        }
    }

    float bb[8];
#pragma unroll
    for (int c = 0; c < 4; c++) { bb[c] = bias[n0 + tx*4 + c]; bb[c+4] = bias[n0 + 64 + tx*4 + c]; }
#pragma unroll
    for (int rh = 0; rh < 2; rh++)
#pragma unroll
        for (int r = 0; r < 4; r++) {
            const int rr = rh * 4 + r;
            float* dst = C + (size_t)(m0 + rh*64 + ty*4 + r) * HID + n0;
            *(float4*)(dst + tx*4)      = make_float4(acc[rr][0]+bb[0], acc[rr][1]+bb[1], acc[rr][2]+bb[2], acc[rr][3]+bb[3]);
            *(float4*)(dst + 64 + tx*4) = make_float4(acc[rr][4]+bb[4], acc[rr][5]+bb[5], acc[rr][6]+bb[6], acc[rr][7]+bb[7]);
        }
}

// S[h][i][j] = (q_i.k_j + q_i.pk_{1024+i-j} + k_j.pq_{1024+i-j})/sqrt(192)
// 128x128 tile; band rows dmin..dmin+254 staged in smem; 8x8 contiguous patch
// per thread needs 15 consecutive band entries: bf[r-c+7].
__global__ __launch_bounds__(256)
void score_kernel()
{
    extern __shared__ float sm[];
    float* qT = sm;                 // [64][128]
    float* kT = sm + 64 * 128;      // [64][128]
    float* bT = sm + 2 * 64 * 128;  // [64][256]

    const int h = blockIdx.z, i0 = blockIdx.y * 128, j0 = blockIdx.x * 128;
    const int t = threadIdx.x, tx = t & 15, ty = t >> 4;

    { const int col = t & 127, dh = (t >> 7) * 32;
      const float* qs = g_q + (size_t)(i0 + col) * HID + h * DHEAD + dh;
      const float* ks = g_k + (size_t)(j0 + col) * HID + h * DHEAD + dh;
#pragma unroll
      for (int f = 0; f < 8; f++) {
          float4 a = *(const float4*)(qs + f*4), b = *(const float4*)(ks + f*4);
          const int d = dh + f*4;
          qT[(d+0)*128+col]=a.x; qT[(d+1)*128+col]=a.y; qT[(d+2)*128+col]=a.z; qT[(d+3)*128+col]=a.w;
          kT[(d+0)*128+col]=b.x; kT[(d+1)*128+col]=b.y; kT[(d+2)*128+col]=b.z; kT[(d+3)*128+col]=b.w;
      } }
    const int dmin = 1024 + i0 - j0 - 127;
    if (t < 255) {
        const float* ps = g_pk + (size_t)(dmin + t) * HID + h * DHEAD;
#pragma unroll
        for (int f = 0; f < 16; f++) {
            float4 a = *(const float4*)(ps + f*4);
            bT[(f*4+0)*256+t]=a.x; bT[(f*4+1)*256+t]=a.y; bT[(f*4+2)*256+t]=a.z; bT[(f*4+3)*256+t]=a.w;
        }
    }
    __syncthreads();

    float acc[8][8];
#pragma unroll
    for (int r = 0; r < 8; r++)
#pragma unroll
        for (int c = 0; c < 8; c++) acc[r][c] = 0.0f;
    const int base = ty*8 - tx*8 + 120;

#pragma unroll 2
    for (int d = 0; d < 64; d++) {
        float4 q0 = *(const float4*)&qT[d*128 + ty*8], q1 = *(const float4*)&qT[d*128 + ty*8 + 4];
        float4 k0 = *(const float4*)&kT[d*128 + tx*8], k1 = *(const float4*)&kT[d*128 + tx*8 + 4];
        float4 f0 = *(const float4*)&bT[d*256 + base],     f1 = *(const float4*)&bT[d*256 + base + 4];
        float4 f2 = *(const float4*)&bT[d*256 + base + 8], f3 = *(const float4*)&bT[d*256 + base + 12];
        float qf[8] = {q0.x,q0.y,q0.z,q0.w, q1.x,q1.y,q1.z,q1.w};
        float kf[8] = {k0.x,k0.y,k0.z,k0.w, k1.x,k1.y,k1.z,k1.w};
        float bf[16] = {f0.x,f0.y,f0.z,f0.w, f1.x,f1.y,f1.z,f1.w,
                        f2.x,f2.y,f2.z,f2.w, f3.x,f3.y,f3.z,f3.w};
#pragma unroll
        for (int r = 0; r < 8; r++)
#pragma unroll
            for (int c = 0; c < 8; c++)
                acc[r][c] = fmaf(qf[r], kf[c] + bf[r-c+7], acc[r][c]);
    }

    __syncthreads();
    if (t < 255) {
        const float* ps = g_pq + (size_t)(dmin + t) * HID + h * DHEAD;
#pragma unroll
        for (int f = 0; f < 16; f++) {
            float4 a = *(const float4*)(ps + f*4);
            bT[(f*4+0)*256+t]=a.x; bT[(f*4+1)*256+t]=a.y; bT[(f*4+2)*256+t]=a.z; bT[(f*4+3)*256+t]=a.w;
        }
    }
    __syncthreads();

#pragma unroll 2
    for (int d = 0; d < 64; d++) {
        float4 k0 = *(const float4*)&kT[d*128 + tx*8], k1 = *(const float4*)&kT[d*128 + tx*8 + 4];
        float4 f0 = *(const float4*)&bT[d*256 + base],     f1 = *(const float4*)&bT[d*256 + base + 4];
        float4 f2 = *(const float4*)&bT[d*256 + base + 8], f3 = *(const float4*)&bT[d*256 + base + 12];
        float kf[8] = {k0.x,k0.y,k0.z,k0.w, k1.x,k1.y,k1.z,k1.w};
        float bf[16] = {f0.x,f0.y,f0.z,f0.w, f1.x,f1.y,f1.z,f1.w,
                        f2.x,f2.y,f2.z,f2.w, f3.x,f3.y,f3.z,f3.w};
#pragma unroll
        for (int r = 0; r < 8; r++)
#pragma unroll
            for (int c = 0; c < 8; c++)
                acc[r][c] = fmaf(kf[c], bf[r-c+7], acc[r][c]);
    }

    const float inv = 0.07216878364870322992f;  // 1/sqrt(192)
#pragma unroll
    for (int r = 0; r < 8; r++) {
        float* dst = g_scores + ((size_t)h * NSEQ + i0 + ty*8 + r) * NSEQ + j0 + tx*8;
        *(float4*)dst     = make_float4(acc[r][0]*inv, acc[r][1]*inv, acc[r][2]*inv, acc[r][3]*inv);
        *(float4*)(dst+4) = make_float4(acc[r][4]*inv, acc[r][5]*inv, acc[r][6]*inv, acc[r][7]*inv);
    }
}

// one warp per (h,i) row: rmax + 1/sum(exp)
__global__ __launch_bounds__(256)
void stats_kernel()
{
    const int w = (blockIdx.x * 256 + threadIdx.x) >> 5;
    const int lane = threadIdx.x & 31;
    const float* row = g_scores + (size_t)w * NSEQ;
    float v[32];
#pragma unroll
    for (int c = 0; c < 8; c++) {
        float4 x = *(const float4*)(row + c*128 + lane*4);
        v[c*4+0]=x.x; v[c*4+1]=x.y; v[c*4+2]=x.z; v[c*4+3]=x.w;
    }
    float m = v[0];
#pragma unroll
    for (int i = 1; i < 32; i++) m = fmaxf(m, v[i]);
#pragma unroll
    for (int o = 16; o > 0; o >>= 1) m = fmaxf(m, __shfl_xor_sync(0xffffffffu, m, o));
    float s = 0.0f;
#pragma unroll
    for (int i = 0; i < 32; i++) s += __expf(v[i] - m);
#pragma unroll
    for (int o = 16; o > 0; o >>= 1) s += __shfl_xor_sync(0xffffffffu, s, o);
    if (lane == 0) { g_rmax[w] = m; g_rinv[w] = 1.0f / s; }
}

// ctx = softmax(S) @ V per head; block = (i-tile, head), 128 thr, BJ=32
__global__ __launch_bounds__(128)
void av_kernel()
{
    const int h = blockIdx.y, i0 = blockIdx.x * 128;
    __shared__ float ps[128][36];
    __shared__ float vs[32][64];
    const int t = threadIdx.x, tx = t & 7, ty = t >> 3;

    float m8[8], ri8[8];
#pragma unroll
    for (int rep = 0; rep < 8; rep++) {
        const int row = rep * 16 + (t >> 3);
        m8[rep] = g_rmax[h * NSEQ + i0 + row];
        ri8[rep] = g_rinv[h * NSEQ + i0 + row];
    }
    float acc[8][8];
#pragma unroll
    for (int r = 0; r < 8; r++)
#pragma unroll
        for (int c = 0; c < 8; c++) acc[r][c] = 0.0f;

    for (int jt = 0; jt < NSEQ; jt += 32) {
        __syncthreads();
#pragma unroll
        for (int rep = 0; rep < 8; rep++) {
            const int v4 = rep * 128 + t, row = v4 >> 3, cq = (v4 & 7) * 4;
            float4 x = *(const float4*)(g_scores + ((size_t)h*NSEQ + i0 + row)*NSEQ + jt + cq);
            const float m = m8[rep], ri = ri8[rep];
            ps[row][cq+0] = __expf(x.x - m) * ri;
            ps[row][cq+1] = __expf(x.y - m) * ri;
            ps[row][cq+2] = __expf(x.z - m) * ri;
            ps[row][cq+3] = __expf(x.w - m) * ri;
        }
#pragma unroll
        for (int rep = 0; rep < 4; rep++) {
            const int u = rep * 128 + t, rv = u >> 4, dq = (u & 15) * 4;
            float4 x = *(const float4*)(g_v + (size_t)(jt + rv)*HID + h*DHEAD + dq);
            vs[rv][dq+0]=x.x; vs[rv][dq+1]=x.y; vs[rv][dq+2]=x.z; vs[rv][dq+3]=x.w;
        }
        __syncthreads();
#pragma unroll 4
        for (int jj = 0; jj < 32; jj++) {
            float vf[8];
            *(float4*)&vf[0] = *(const float4*)&vs[jj][tx*8];
            *(float4*)&vf[4] = *(const float4*)&vs[jj][tx*8+4];
            float pf[8];
#pragma unroll
            for (int r = 0; r < 8; r++) pf[r] = ps[ty*8+r][jj];
#pragma unroll
            for (int r = 0; r < 8; r++)
#pragma unroll
                for (int c = 0; c < 8; c++) acc[r][c] = fmaf(pf[r], vf[c], acc[r][c]);
        }
    }
#pragma unroll
    for (int r = 0; r < 8; r++) {
        float* dst = g_ctx + (size_t)(i0 + ty*8 + r)*HID + h*DHEAD + tx*8;
        *(float4*)dst     = make_float4(acc[r][0], acc[r][1], acc[r][2], acc[r][3]);
        *(float4*)(dst+4) = make_float4(acc[r][4], acc[r][5], acc[r][6], acc[r][7]);
    }
}

// out = LN(proj + hs)*g + b, one block/row
__global__ __launch_bounds__(256)
void ln_kernel(const float* __restrict__ hs, const float* __restrict__ gg,
               const float* __restrict__ bb, float* __restrict__ out)
{
    const int row = blockIdx.x, t = threadIdx.x;
    __shared__ float red[8];
    float4 p = *(const float4*)(g_proj + (size_t)row*HID + t*4);
    float4 hv = *(const float4*)(hs + (size_t)row*HID + t*4);
    float x0 = p.x+hv.x, x1 = p.y+hv.y, x2 = p.z+hv.z, x3 = p.w+hv.w;
    float s = x0+x1+x2+x3;
#pragma unroll
    for (int o = 16; o > 0; o >>= 1) s += __shfl_xor_sync(0xffffffffu, s, o);
    if ((t & 31) == 0) red[t >> 5] = s;
    __syncthreads();
    float mu = (red[0]+red[1]+red[2]+red[3]+red[4]+red[5]+red[6]+red[7]) * (1.0f/1024.0f);
    float d0 = x0-mu, d1 = x1-mu, d2 = x2-mu, d3 = x3-mu;
    float sq = d0*d0 + d1*d1 + d2*d2 + d3*d3;
#pragma unroll
    for (int o = 16; o > 0; o >>= 1) sq += __shfl_xor_sync(0xffffffffu, sq, o);
    __syncthreads();
    if ((t & 31) == 0) red[t >> 5] = sq;
    __syncthreads();
    float var = (red[0]+red[1]+red[2]+red[3]+red[4]+red[5]+red[6]+red[7]) * (1.0f/1024.0f);
    float rstd = rsqrtf(var + 1e-7f);
    float4 g4 = *(const float4*)(gg + t*4);
    float4 b4 = *(const float4*)(bb + t*4);
    *(float4*)(out + (size_t)row*HID + t*4) =
        make_float4(d0*rstd*g4.x + b4.x, d1*rstd*g4.y + b4.y,
                    d2*rstd*g4.z + b4.z, d3*rstd*g4.w + b4.w);
}

extern "C" void kernel_launch(void* const* d_in, const int* in_sizes, int n_in,
                              void* d_out, int out_size)
{
    const float* hs  = (const float*)d_in[0];
    const float* rel = (const float*)d_in[1];
    const float* Wq  = (const float*)d_in[2];  const float* bq  = (const float*)d_in[3];
    const float* Wk  = (const float*)d_in[4];  const float* bk  = (const float*)d_in[5];
    const float* Wv  = (const float*)d_in[6];  const float* bv  = (const float*)d_in[7];
    const float* Wpk = (const float*)d_in[8];  const float* bpk = (const float*)d_in[9];
    const float* Wpq = (const float*)d_in[10]; const float* bpq = (const float*)d_in[11];
    const float* Wo  = (const float*)d_in[12]; const float* bo  = (const float*)d_in[13];
    const float* lng = (const float*)d_in[14]; const float* lnb = (const float*)d_in[15];

    float *q_, *k_, *v_, *pk_, *pq_, *ctx_, *proj_;
    cudaGetSymbolAddress((void**)&q_, g_q);
    cudaGetSymbolAddress((void**)&k_, g_k);
    cudaGetSymbolAddress((void**)&v_, g_v);
    cudaGetSymbolAddress((void**)&pk_, g_pk);
    cudaGetSymbolAddress((void**)&pq_, g_pq);
    cudaGetSymbolAddress((void**)&ctx_, g_ctx);
    cudaGetSymbolAddress((void**)&proj_, g_proj);

    static int smem_set = 0;
    if (!smem_set) {
        cudaFuncSetAttribute(score_kernel, cudaFuncAttributeMaxDynamicSharedMemorySize, 131072);
        smem_set = 1;
    }

    gemm_nt<<<dim3(8, 8, 3), 256>>>(hs, Wq, bq, q_, Wk, bk, k_, Wv, bv, v_);
    gemm_nt<<<dim3(8, 16, 2), 256>>>(rel, Wpk, bpk, pk_, Wpq, bpq, pq_, Wpq, bpq, pq_);
    score_kernel<<<dim3(8, 8, 16), 256, 131072>>>();
    stats_kernel<<<2048, 256>>>();
    av_kernel<<<dim3(8, 16), 128>>>();
    gemm_nt<<<dim3(8, 8, 1), 256>>>(ctx_, Wo, bo, proj_, Wo, bo, proj_, Wo, bo, proj_);
    ln_kernel<<<1024, 256>>>(hs, lng, lnb, (float*)d_out);
}

// round 4
// speedup vs baseline: 1.8717x; 1.8717x over previous
#include <cuda_runtime.h>
#include <stdint.h>

#define HID   1024
#define NSEQ  1024
#define DHEAD 64

__device__ float g_q[NSEQ * HID];
__device__ float g_k[NSEQ * HID];
__device__ float g_v[NSEQ * HID];
__device__ float g_pk[2048 * HID];
__device__ float g_pq[2048 * HID];
__device__ float g_scores[16 * NSEQ * NSEQ];
__device__ float g_rmax[16 * NSEQ];
__device__ float g_rinv[16 * NSEQ];
__device__ float g_ctx[NSEQ * HID];
__device__ float g_proj[NSEQ * HID];

__device__ __forceinline__ uint32_t f2tf(float x) {
    uint32_t u; asm("cvt.rna.tf32.f32 %0, %1;" : "=r"(u) : "f"(x)); return u;
}
__device__ __forceinline__ void mma8(float* c, const uint32_t* a, const uint32_t* b) {
    asm volatile(
        "mma.sync.aligned.m16n8k8.row.col.f32.tf32.tf32.f32 "
        "{%0,%1,%2,%3}, {%4,%5,%6,%7}, {%8,%9}, {%0,%1,%2,%3};\n"
        : "+f"(c[0]), "+f"(c[1]), "+f"(c[2]), "+f"(c[3])
        : "r"(a[0]), "r"(a[1]), "r"(a[2]), "r"(a[3]), "r"(b[0]), "r"(b[1]));
}

// ============== tf32 NT GEMM: C[m][n] = sum_k A[m][k]*W[n][k] + b[n] ==========
// block 128x128, 256 thr, 8 warps (2x4), warp tile 64x32, BK=32, double-buffer.
__global__ __launch_bounds__(256)
void gemm_tf32(const float* __restrict__ A,
               const float* __restrict__ W0, const float* __restrict__ b0, float* __restrict__ C0,
               const float* __restrict__ W1, const float* __restrict__ b1, float* __restrict__ C1,
               const float* __restrict__ W2, const float* __restrict__ b2, float* __restrict__ C2)
{
    extern __shared__ uint32_t sh[];
    uint32_t* As = sh;                 // [2][128][36]
    uint32_t* Ws = sh + 2 * 128 * 36;  // [2][128][36]

    const int z = blockIdx.z;
    const float* W    = (z == 0) ? W0 : ((z == 1) ? W1 : W2);
    const float* bias = (z == 0) ? b0 : ((z == 1) ? b1 : b2);
    float*       C    = (z == 0) ? C0 : ((z == 1) ? C1 : C2);

    const int m0 = blockIdx.y * 128, n0 = blockIdx.x * 128;
    const int t = threadIdx.x, lane = t & 31, warp = t >> 5;
    const int g = lane >> 2, qd = lane & 3;
    const int wm = warp >> 2, wn = warp & 3;

    const int lrow = t >> 1, lkoff = (t & 1) * 16;
    const float* Ap = A + (size_t)(m0 + lrow) * HID + lkoff;
    const float* Wp = W + (size_t)(n0 + lrow) * HID + lkoff;

#pragma unroll
    for (int f = 0; f < 4; f++) {
        float4 va = *(const float4*)(Ap + f * 4);
        float4 vw = *(const float4*)(Wp + f * 4);
        *(uint4*)&As[lrow * 36 + lkoff + f * 4] =
            make_uint4(f2tf(va.x), f2tf(va.y), f2tf(va.z), f2tf(va.w));
        *(uint4*)&Ws[lrow * 36 + lkoff + f * 4] =
            make_uint4(f2tf(vw.x), f2tf(vw.y), f2tf(vw.z), f2tf(vw.w));
    }
    __syncthreads();

    float acc[4][4][4];
#pragma unroll
    for (int i = 0; i < 4; i++)
#pragma unroll
        for (int j = 0; j < 4; j++)
#pragma unroll
            for (int e = 0; e < 4; e++) acc[i][j][e] = 0.0f;

    for (int kt = 0; kt < 32; kt++) {
        const int cur = kt & 1;
        float4 pa[4], pw[4];
        const bool more = (kt + 1 < 32);
        if (more) {
#pragma unroll
            for (int f = 0; f < 4; f++) {
                pa[f] = *(const float4*)(Ap + (kt + 1) * 32 + f * 4);
                pw[f] = *(const float4*)(Wp + (kt + 1) * 32 + f * 4);
            }
        }
        const uint32_t* Ab = As + cur * 4608;
        const uint32_t* Bb = Ws + cur * 4608;
#pragma unroll
        for (int kk = 0; kk < 4; kk++) {
            uint32_t af[4][4], bf[4][2];
#pragma unroll
            for (int tm = 0; tm < 4; tm++) {
                const int row = wm * 64 + tm * 16 + g;
                af[tm][0] = Ab[row * 36 + kk * 8 + qd];
                af[tm][1] = Ab[(row + 8) * 36 + kk * 8 + qd];
                af[tm][2] = Ab[row * 36 + kk * 8 + qd + 4];
                af[tm][3] = Ab[(row + 8) * 36 + kk * 8 + qd + 4];
            }
#pragma unroll
            for (int tn = 0; tn < 4; tn++) {
                const int col = wn * 32 + tn * 8 + g;
                bf[tn][0] = Bb[col * 36 + kk * 8 + qd];
                bf[tn][1] = Bb[col * 36 + kk * 8 + qd + 4];
            }
#pragma unroll
            for (int tm = 0; tm < 4; tm++)
#pragma unroll
                for (int tn = 0; tn < 4; tn++) mma8(acc[tm][tn], af[tm], bf[tn]);
        }
        if (more) {
            const int nx = cur ^ 1;
#pragma unroll
            for (int f = 0; f < 4; f++) {
                *(uint4*)&As[nx * 4608 + lrow * 36 + lkoff + f * 4] =
                    make_uint4(f2tf(pa[f].x), f2tf(pa[f].y), f2tf(pa[f].z), f2tf(pa[f].w));
                *(uint4*)&Ws[nx * 4608 + lrow * 36 + lkoff + f * 4] =
                    make_uint4(f2tf(pw[f].x), f2tf(pw[f].y), f2tf(pw[f].z), f2tf(pw[f].w));
            }
            __syncthreads();
        }
    }

#pragma unroll
    for (int tm = 0; tm < 4; tm++)
#pragma unroll
        for (int tn = 0; tn < 4; tn++) {
            const int row = m0 + wm * 64 + tm * 16 + g;
            const int col = n0 + wn * 32 + tn * 8 + 2 * qd;
            const float bv0 = bias[col], bv1 = bias[col + 1];
            *(float2*)&C[(size_t)row * HID + col] =
                make_float2(acc[tm][tn][0] + bv0, acc[tm][tn][1] + bv1);
            *(float2*)&C[(size_t)(row + 8) * HID + col] =
                make_float2(acc[tm][tn][2] + bv0, acc[tm][tn][3] + bv1);
        }
}

// ============== score: S = (q.k + q.pk_band + k.pq_band)/sqrt(192) ===========
// 128x128 tile; band GEMMs [128x256] in two 128-col halves + smem gather.
__global__ __launch_bounds__(256)
void score_mma()
{
    extern __shared__ float smf[];
    uint32_t* qS = (uint32_t*)smf;       // [128][68]
    uint32_t* kS = qS + 128 * 68;        // [128][68]
    uint32_t* bS = kS + 128 * 68;        // [256][68]
    float*    Gs = (float*)(bS + 256 * 68);  // [128][132]

    const int h = blockIdx.z, i0 = blockIdx.y * 128, j0 = blockIdx.x * 128;
    const int t = threadIdx.x, lane = t & 31, warp = t >> 5;
    const int g = lane >> 2, qd = lane & 3;
    const int wm = warp >> 2, wn = warp & 3;

    // stage q, k (tf32)
    {
        const int lrow = t >> 1, dh = (t & 1) * 32;
        const float* qp = g_q + (size_t)(i0 + lrow) * HID + h * DHEAD + dh;
        const float* kp = g_k + (size_t)(j0 + lrow) * HID + h * DHEAD + dh;
#pragma unroll
        for (int f = 0; f < 8; f++) {
            float4 a = *(const float4*)(qp + f * 4);
            float4 b = *(const float4*)(kp + f * 4);
            *(uint4*)&qS[lrow * 68 + dh + f * 4] =
                make_uint4(f2tf(a.x), f2tf(a.y), f2tf(a.z), f2tf(a.w));
            *(uint4*)&kS[lrow * 68 + dh + f * 4] =
                make_uint4(f2tf(b.x), f2tf(b.y), f2tf(b.z), f2tf(b.w));
        }
    }
    const int dmin = 1024 + i0 - j0 - 127;
    {
        const int brow = (t < 255) ? t : 254;
        const float* bp = g_pk + (size_t)(dmin + brow) * HID + h * DHEAD;
#pragma unroll
        for (int f = 0; f < 16; f++) {
            float4 a = *(const float4*)(bp + f * 4);
            *(uint4*)&bS[t * 68 + f * 4] =
                make_uint4(f2tf(a.x), f2tf(a.y), f2tf(a.z), f2tf(a.w));
        }
    }
    __syncthreads();

    float S[4][4][4];
#pragma unroll
    for (int i = 0; i < 4; i++)
#pragma unroll
        for (int j = 0; j < 4; j++)
#pragma unroll
            for (int e = 0; e < 4; e++) S[i][j][e] = 0.0f;

    // QK
#pragma unroll
    for (int kk = 0; kk < 8; kk++) {
        uint32_t af[4][4], bf[4][2];
#pragma unroll
        for (int tm = 0; tm < 4; tm++) {
            const int row = wm * 64 + tm * 16 + g;
            af[tm][0] = qS[row * 68 + kk * 8 + qd];
            af[tm][1] = qS[(row + 8) * 68 + kk * 8 + qd];
            af[tm][2] = qS[row * 68 + kk * 8 + qd + 4];
            af[tm][3] = qS[(row + 8) * 68 + kk * 8 + qd + 4];
        }
#pragma unroll
        for (int tn = 0; tn < 4; tn++) {
            const int col = wn * 32 + tn * 8 + g;
            bf[tn][0] = kS[col * 68 + kk * 8 + qd];
            bf[tn][1] = kS[col * 68 + kk * 8 + qd + 4];
        }
#pragma unroll
        for (int tm = 0; tm < 4; tm++)
#pragma unroll
            for (int tn = 0; tn < 4; tn++) mma8(S[tm][tn], af[tm], bf[tn]);
    }

    // position passes: pass 0 = c2p (q x pk_band), pass 1 = p2c (k x pq_band)
    for (int pass = 0; pass < 2; pass++) {
        if (pass == 1) {
            const int brow = (t < 255) ? t : 254;
            const float* bp = g_pq + (size_t)(dmin + brow) * HID + h * DHEAD;
#pragma unroll
            for (int f = 0; f < 16; f++) {
                float4 a = *(const float4*)(bp + f * 4);
                *(uint4*)&bS[t * 68 + f * 4] =
                    make_uint4(f2tf(a.x), f2tf(a.y), f2tf(a.z), f2tf(a.w));
            }
            __syncthreads();
        }
        const uint32_t* X = (pass == 0) ? qS : kS;
        for (int bh = 0; bh < 2; bh++) {
            float Ga[4][4][4];
#pragma unroll
            for (int i = 0; i < 4; i++)
#pragma unroll
                for (int j = 0; j < 4; j++)
#pragma unroll
                    for (int e = 0; e < 4; e++) Ga[i][j][e] = 0.0f;
#pragma unroll
            for (int kk = 0; kk < 8; kk++) {
                uint32_t af[4][4], bf[4][2];
#pragma unroll
                for (int tm = 0; tm < 4; tm++) {
                    const int row = wm * 64 + tm * 16 + g;
                    af[tm][0] = X[row * 68 + kk * 8 + qd];
                    af[tm][1] = X[(row + 8) * 68 + kk * 8 + qd];
                    af[tm][2] = X[row * 68 + kk * 8 + qd + 4];
                    af[tm][3] = X[(row + 8) * 68 + kk * 8 + qd + 4];
                }
#pragma unroll
                for (int tn = 0; tn < 4; tn++) {
                    const int b = bh * 128 + wn * 32 + tn * 8 + g;
                    bf[tn][0] = bS[b * 68 + kk * 8 + qd];
                    bf[tn][1] = bS[b * 68 + kk * 8 + qd + 4];
                }
#pragma unroll
                for (int tm = 0; tm < 4; tm++)
#pragma unroll
                    for (int tn = 0; tn < 4; tn++) mma8(Ga[tm][tn], af[tm], bf[tn]);
            }
            // store G half to smem
#pragma unroll
            for (int tm = 0; tm < 4; tm++)
#pragma unroll
                for (int tn = 0; tn < 4; tn++) {
                    const int r = wm * 64 + tm * 16 + g;
                    const int c = wn * 32 + tn * 8 + 2 * qd;
                    *(float2*)&Gs[r * 132 + c] = make_float2(Ga[tm][tn][0], Ga[tm][tn][1]);
                    *(float2*)&Gs[(r + 8) * 132 + c] = make_float2(Ga[tm][tn][2], Ga[tm][tn][3]);
                }
            __syncthreads();
            // gather band contributions into S
#pragma unroll
            for (int tm = 0; tm < 4; tm++)
#pragma unroll
                for (int tn = 0; tn < 4; tn++) {
                    const int il = wm * 64 + tm * 16 + g;
                    const int jl = wn * 32 + tn * 8 + 2 * qd;
                    const int b0v = il - jl + 127 - bh * 128;
                    const int bv[4] = {b0v, b0v - 1, b0v + 8, b0v + 7};
                    int rv[4];
                    if (pass == 0) { rv[0] = il; rv[1] = il; rv[2] = il + 8; rv[3] = il + 8; }
                    else           { rv[0] = jl; rv[1] = jl + 1; rv[2] = jl; rv[3] = jl + 1; }
#pragma unroll
                    for (int e = 0; e < 4; e++)
                        if ((unsigned)bv[e] < 128u)
                            S[tm][tn][e] += Gs[rv[e] * 132 + bv[e]];
                }
            __syncthreads();
        }
    }

    const float inv = 0.07216878364870322992f;  // 1/sqrt(192)
#pragma unroll
    for (int tm = 0; tm < 4; tm++)
#pragma unroll
        for (int tn = 0; tn < 4; tn++) {
            const int row = i0 + wm * 64 + tm * 16 + g;
            const int col = j0 + wn * 32 + tn * 8 + 2 * qd;
            float* o0 = g_scores + ((size_t)h * NSEQ + row) * NSEQ + col;
            float* o1 = g_scores + ((size_t)h * NSEQ + row + 8) * NSEQ + col;
            *(float2*)o0 = make_float2(S[tm][tn][0] * inv, S[tm][tn][1] * inv);
            *(float2*)o1 = make_float2(S[tm][tn][2] * inv, S[tm][tn][3] * inv);
        }
}

// ============== stats: one warp per (h,i) row ================================
__global__ __launch_bounds__(256)
void stats_kernel()
{
    const int w = (blockIdx.x * 256 + threadIdx.x) >> 5;
    const int lane = threadIdx.x & 31;
    const float* row = g_scores + (size_t)w * NSEQ;
    float v[32];
#pragma unroll
    for (int c = 0; c < 8; c++) {
        float4 x = *(const float4*)(row + c * 128 + lane * 4);
        v[c*4+0]=x.x; v[c*4+1]=x.y; v[c*4+2]=x.z; v[c*4+3]=x.w;
    }
    float m = v[0];
#pragma unroll
    for (int i = 1; i < 32; i++) m = fmaxf(m, v[i]);
#pragma unroll
    for (int o = 16; o > 0; o >>= 1) m = fmaxf(m, __shfl_xor_sync(0xffffffffu, m, o));
    float s = 0.0f;
#pragma unroll
    for (int i = 0; i < 32; i++) s += __expf(v[i] - m);
#pragma unroll
    for (int o = 16; o > 0; o >>= 1) s += __shfl_xor_sync(0xffffffffu, s, o);
    if (lane == 0) { g_rmax[w] = m; g_rinv[w] = 1.0f / s; }
}

// ============== AV: ctx = softmax(S) @ V via tf32 mma ========================
// block (i-tile 128, head), 256 thr, warp grid 2x4, warp tile 64x16, BJ=32.
__global__ __launch_bounds__(256)
void av_mma()
{
    __shared__ uint32_t Ps[128 * 36];  // P tf32, [i][j]
    __shared__ uint32_t Vt[64 * 36];   // V transposed tf32, [d][j]
    const int h = blockIdx.y, i0 = blockIdx.x * 128;
    const int t = threadIdx.x, lane = t & 31, warp = t >> 5;
    const int g = lane >> 2, qd = lane & 3;
    const int wm = warp >> 2, wn = warp & 3;

    const int lrow = t >> 1, lj = (t & 1) * 16;
    const float m  = g_rmax[h * NSEQ + i0 + lrow];
    const float ri = g_rinv[h * NSEQ + i0 + lrow];

    float acc[4][2][4];
#pragma unroll
    for (int i = 0; i < 4; i++)
#pragma unroll
        for (int j = 0; j < 2; j++)
#pragma unroll
            for (int e = 0; e < 4; e++) acc[i][j][e] = 0.0f;

    for (int jt = 0; jt < NSEQ; jt += 32) {
        __syncthreads();
        // stage P = exp(S - m) * ri
        const float* sp = g_scores + ((size_t)h * NSEQ + i0 + lrow) * NSEQ + jt + lj;
#pragma unroll
        for (int f = 0; f < 4; f++) {
            float4 x = *(const float4*)(sp + f * 4);
            *(uint4*)&Ps[lrow * 36 + lj + f * 4] = make_uint4(
                f2tf(__expf(x.x - m) * ri), f2tf(__expf(x.y - m) * ri),
                f2tf(__expf(x.z - m) * ri), f2tf(__expf(x.w - m) * ri));
        }
        // stage V transposed: Vt[d][j]
        {
            const int vr = t >> 3, dblk = (t & 7) * 8;
            const float* vp = g_v + (size_t)(jt + vr) * HID + h * DHEAD + dblk;
            float4 a = *(const float4*)vp;
            float4 b = *(const float4*)(vp + 4);
            Vt[(dblk + 0) * 36 + vr] = f2tf(a.x); Vt[(dblk + 1) * 36 + vr] = f2tf(a.y);
            Vt[(dblk + 2) * 36 + vr] = f2tf(a.z); Vt[(dblk + 3) * 36 + vr] = f2tf(a.w);
            Vt[(dblk + 4) * 36 + vr] = f2tf(b.x); Vt[(dblk + 5) * 36 + vr] = f2tf(b.y);
            Vt[(dblk + 6) * 36 + vr] = f2tf(b.z); Vt[(dblk + 7) * 36 + vr] = f2tf(b.w);
        }
        __syncthreads();
#pragma unroll
        for (int kk = 0; kk < 4; kk++) {
            uint32_t af[4][4], bf[2][2];
#pragma unroll
            for (int tm = 0; tm < 4; tm++) {
                const int row = wm * 64 + tm * 16 + g;
                af[tm][0] = Ps[row * 36 + kk * 8 + qd];
                af[tm][1] = Ps[(row + 8) * 36 + kk * 8 + qd];
                af[tm][2] = Ps[row * 36 + kk * 8 + qd + 4];
                af[tm][3] = Ps[(row + 8) * 36 + kk * 8 + qd + 4];
            }
#pragma unroll
            for (int tn = 0; tn < 2; tn++) {
                const int col = wn * 16 + tn * 8 + g;
                bf[tn][0] = Vt[col * 36 + kk * 8 + qd];
                bf[tn][1] = Vt[col * 36 + kk * 8 + qd + 4];
            }
#pragma unroll
            for (int tm = 0; tm < 4; tm++)
#pragma unroll
                for (int tn = 0; tn < 2; tn++) mma8(acc[tm][tn], af[tm], bf[tn]);
        }
    }
#pragma unroll
    for (int tm = 0; tm < 4; tm++)
#pragma unroll
        for (int tn = 0; tn < 2; tn++) {
            const int row = i0 + wm * 64 + tm * 16 + g;
            const int col = h * DHEAD + wn * 16 + tn * 8 + 2 * qd;
            *(float2*)&g_ctx[(size_t)row * HID + col] =
                make_float2(acc[tm][tn][0], acc[tm][tn][1]);
            *(float2*)&g_ctx[(size_t)(row + 8) * HID + col] =
                make_float2(acc[tm][tn][2], acc[tm][tn][3]);
        }
}

// ============== residual + LayerNorm =========================================
__global__ __launch_bounds__(256)
void ln_kernel(const float* __restrict__ hs, const float* __restrict__ gg,
               const float* __restrict__ bb, float* __restrict__ out)
{
    const int row = blockIdx.x, t = threadIdx.x;
    __shared__ float red[8];
    float4 p = *(const float4*)(g_proj + (size_t)row * HID + t * 4);
    float4 hv = *(const float4*)(hs + (size_t)row * HID + t * 4);
    float x0 = p.x+hv.x, x1 = p.y+hv.y, x2 = p.z+hv.z, x3 = p.w+hv.w;
    float s = x0+x1+x2+x3;
#pragma unroll
    for (int o = 16; o > 0; o >>= 1) s += __shfl_xor_sync(0xffffffffu, s, o);
    if ((t & 31) == 0) red[t >> 5] = s;
    __syncthreads();
    float mu = (red[0]+red[1]+red[2]+red[3]+red[4]+red[5]+red[6]+red[7]) * (1.0f/1024.0f);
    float d0 = x0-mu, d1 = x1-mu, d2 = x2-mu, d3 = x3-mu;
    float sq = d0*d0 + d1*d1 + d2*d2 + d3*d3;
#pragma unroll
    for (int o = 16; o > 0; o >>= 1) sq += __shfl_xor_sync(0xffffffffu, sq, o);
    __syncthreads();
    if ((t & 31) == 0) red[t >> 5] = sq;
    __syncthreads();
    float var = (red[0]+red[1]+red[2]+red[3]+red[4]+red[5]+red[6]+red[7]) * (1.0f/1024.0f);
    float rstd = rsqrtf(var + 1e-7f);
    float4 g4 = *(const float4*)(gg + t * 4);
    float4 b4 = *(const float4*)(bb + t * 4);
    *(float4*)(out + (size_t)row * HID + t * 4) =
        make_float4(d0*rstd*g4.x + b4.x, d1*rstd*g4.y + b4.y,
                    d2*rstd*g4.z + b4.z, d3*rstd*g4.w + b4.w);
}

extern "C" void kernel_launch(void* const* d_in, const int* in_sizes, int n_in,
                              void* d_out, int out_size)
{
    const float* hs  = (const float*)d_in[0];
    const float* rel = (const float*)d_in[1];
    const float* Wq  = (const float*)d_in[2];  const float* bq  = (const float*)d_in[3];
    const float* Wk  = (const float*)d_in[4];  const float* bk  = (const float*)d_in[5];
    const float* Wv  = (const float*)d_in[6];  const float* bv  = (const float*)d_in[7];
    const float* Wpk = (const float*)d_in[8];  const float* bpk = (const float*)d_in[9];
    const float* Wpq = (const float*)d_in[10]; const float* bpq = (const float*)d_in[11];
    const float* Wo  = (const float*)d_in[12]; const float* bo  = (const float*)d_in[13];
    const float* lng = (const float*)d_in[14]; const float* lnb = (const float*)d_in[15];

    float *q_, *k_, *v_, *pk_, *pq_, *ctx_, *proj_;
    cudaGetSymbolAddress((void**)&q_, g_q);
    cudaGetSymbolAddress((void**)&k_, g_k);
    cudaGetSymbolAddress((void**)&v_, g_v);
    cudaGetSymbolAddress((void**)&pk_, g_pk);
    cudaGetSymbolAddress((void**)&pq_, g_pq);
    cudaGetSymbolAddress((void**)&ctx_, g_ctx);
    cudaGetSymbolAddress((void**)&proj_, g_proj);

    cudaFuncSetAttribute(gemm_tf32, cudaFuncAttributeMaxDynamicSharedMemorySize, 73728);
    cudaFuncSetAttribute(score_mma, cudaFuncAttributeMaxDynamicSharedMemorySize, 206848);

    gemm_tf32<<<dim3(8, 8, 3), 256, 73728>>>(hs, Wq, bq, q_, Wk, bk, k_, Wv, bv, v_);
    gemm_tf32<<<dim3(8, 16, 2), 256, 73728>>>(rel, Wpk, bpk, pk_, Wpq, bpq, pq_, Wpq, bpq, pq_);
    score_mma<<<dim3(8, 8, 16), 256, 206848>>>();
    stats_kernel<<<2048, 256>>>();
    av_mma<<<dim3(8, 16), 256>>>();
    gemm_tf32<<<dim3(8, 8, 1), 256, 73728>>>(ctx_, Wo, bo, proj_, Wo, bo, proj_, Wo, bo, proj_);
    ln_kernel<<<1024, 256>>>(hs, lng, lnb, (float*)d_out);
}

// round 5
// speedup vs baseline: 2.4603x; 1.3145x over previous
#include <cuda_runtime.h>
#include <cuda_bf16.h>
#include <stdint.h>

#define HID   1024
#define NSEQ  1024
#define DHEAD 64

__device__ float g_q[NSEQ * HID];
__device__ float g_k[NSEQ * HID];
__device__ float g_v[NSEQ * HID];
__device__ float g_pk[2048 * HID];
__device__ float g_pq[2048 * HID];
__device__ float g_scores[16 * NSEQ * NSEQ];
__device__ float g_rmax[16 * NSEQ];
__device__ float g_rinv[16 * NSEQ];
__device__ float g_ctx[NSEQ * HID];
__device__ float g_proj[NSEQ * HID];

// pack two fp32 -> bf16x2 (lo = first arg)
__device__ __forceinline__ uint32_t f2bf2(float lo, float hi) {
    uint32_t r;
    asm("cvt.rn.bf16x2.f32 %0, %1, %2;" : "=r"(r) : "f"(hi), "f"(lo));
    return r;
}
__device__ __forceinline__ void mma16(float* c, const uint32_t* a, const uint32_t* b) {
    asm volatile(
        "mma.sync.aligned.m16n8k16.row.col.f32.bf16.bf16.f32 "
        "{%0,%1,%2,%3}, {%4,%5,%6,%7}, {%8,%9}, {%0,%1,%2,%3};\n"
        : "+f"(c[0]), "+f"(c[1]), "+f"(c[2]), "+f"(c[3])
        : "r"(a[0]), "r"(a[1]), "r"(a[2]), "r"(a[3]), "r"(b[0]), "r"(b[1]));
}

#define ASTRIDE 40   // 32 K + 8 pad (bf16 elems)

// ============== bf16 NT GEMM: C[m][n] = sum_k A[m][k]*W[n][k] + b[n] =========
// block 128x128, 256 thr, 8 warps (2x4), warp tile 64x32, BK=32, double-buffer.
__global__ __launch_bounds__(256)
void gemm_bf16(const float* __restrict__ A,
               const float* __restrict__ W0, const float* __restrict__ b0, float* __restrict__ C0,
               const float* __restrict__ W1, const float* __restrict__ b1, float* __restrict__ C1,
               const float* __restrict__ W2, const float* __restrict__ b2, float* __restrict__ C2)
{
    __shared__ __nv_bfloat16 As[2][128 * ASTRIDE];
    __shared__ __nv_bfloat16 Ws[2][128 * ASTRIDE];

    const int z = blockIdx.z;
    const float* W    = (z == 0) ? W0 : ((z == 1) ? W1 : W2);
    const float* bias = (z == 0) ? b0 : ((z == 1) ? b1 : b2);
    float*       C    = (z == 0) ? C0 : ((z == 1) ? C1 : C2);

    const int m0 = blockIdx.y * 128, n0 = blockIdx.x * 128;
    const int t = threadIdx.x, lane = t & 31, warp = t >> 5;
    const int g = lane >> 2, qd = lane & 3;
    const int wm = warp >> 2, wn = warp & 3;

    const int lrow = t >> 1, lkoff = (t & 1) * 16;
    const float* Ap = A + (size_t)(m0 + lrow) * HID + lkoff;
    const float* Wp = W + (size_t)(n0 + lrow) * HID + lkoff;

    // stage tile 0
    {
        uint32_t pa[8], pw[8];
#pragma unroll
        for (int f = 0; f < 4; f++) {
            float4 va = *(const float4*)(Ap + f * 4);
            float4 vw = *(const float4*)(Wp + f * 4);
            pa[f*2]   = f2bf2(va.x, va.y); pa[f*2+1] = f2bf2(va.z, va.w);
            pw[f*2]   = f2bf2(vw.x, vw.y); pw[f*2+1] = f2bf2(vw.z, vw.w);
        }
        uint32_t* da = (uint32_t*)&As[0][lrow * ASTRIDE + lkoff];
        uint32_t* dw = (uint32_t*)&Ws[0][lrow * ASTRIDE + lkoff];
        *(uint4*)da       = make_uint4(pa[0], pa[1], pa[2], pa[3]);
        *(uint4*)(da + 4) = make_uint4(pa[4], pa[5], pa[6], pa[7]);
        *(uint4*)dw       = make_uint4(pw[0], pw[1], pw[2], pw[3]);
        *(uint4*)(dw + 4) = make_uint4(pw[4], pw[5], pw[6], pw[7]);
    }
    __syncthreads();

    float acc[4][4][4];
#pragma unroll
    for (int i = 0; i < 4; i++)
#pragma unroll
        for (int j = 0; j < 4; j++)
#pragma unroll
            for (int e = 0; e < 4; e++) acc[i][j][e] = 0.0f;

    for (int kt = 0; kt < 32; kt++) {
        const int cur = kt & 1;
        float4 pa[4], pw[4];
        const bool more = (kt + 1 < 32);
        if (more) {
#pragma unroll
            for (int f = 0; f < 4; f++) {
                pa[f] = *(const float4*)(Ap + (kt + 1) * 32 + f * 4);
                pw[f] = *(const float4*)(Wp + (kt + 1) * 32 + f * 4);
            }
        }
        const __nv_bfloat16* Ab = As[cur];
        const __nv_bfloat16* Bb = Ws[cur];
#pragma unroll
        for (int kk = 0; kk < 2; kk++) {
            uint32_t af[4][4], bf[4][2];
#pragma unroll
            for (int tm = 0; tm < 4; tm++) {
                const int row = wm * 64 + tm * 16 + g;
                af[tm][0] = *(const uint32_t*)&Ab[row * ASTRIDE + kk * 16 + 2 * qd];
                af[tm][1] = *(const uint32_t*)&Ab[(row + 8) * ASTRIDE + kk * 16 + 2 * qd];
                af[tm][2] = *(const uint32_t*)&Ab[row * ASTRIDE + kk * 16 + 2 * qd + 8];
                af[tm][3] = *(const uint32_t*)&Ab[(row + 8) * ASTRIDE + kk * 16 + 2 * qd + 8];
            }
#pragma unroll
            for (int tn = 0; tn < 4; tn++) {
                const int col = wn * 32 + tn * 8 + g;
                bf[tn][0] = *(const uint32_t*)&Bb[col * ASTRIDE + kk * 16 + 2 * qd];
                bf[tn][1] = *(const uint32_t*)&Bb[col * ASTRIDE + kk * 16 + 2 * qd + 8];
            }
#pragma unroll
            for (int tm = 0; tm < 4; tm++)
#pragma unroll
                for (int tn = 0; tn < 4; tn++) mma16(acc[tm][tn], af[tm], bf[tn]);
        }
        if (more) {
            const int nx = cur ^ 1;
            uint32_t qa[8], qw[8];
#pragma unroll
            for (int f = 0; f < 4; f++) {
                qa[f*2]   = f2bf2(pa[f].x, pa[f].y); qa[f*2+1] = f2bf2(pa[f].z, pa[f].w);
                qw[f*2]   = f2bf2(pw[f].x, pw[f].y); qw[f*2+1] = f2bf2(pw[f].z, pw[f].w);
            }
            uint32_t* da = (uint32_t*)&As[nx][lrow * ASTRIDE + lkoff];
            uint32_t* dw = (uint32_t*)&Ws[nx][lrow * ASTRIDE + lkoff];
            *(uint4*)da       = make_uint4(qa[0], qa[1], qa[2], qa[3]);
            *(uint4*)(da + 4) = make_uint4(qa[4], qa[5], qa[6], qa[7]);
            *(uint4*)dw       = make_uint4(qw[0], qw[1], qw[2], qw[3]);
            *(uint4*)(dw + 4) = make_uint4(qw[4], qw[5], qw[6], qw[7]);
            __syncthreads();
        }
    }

#pragma unroll
    for (int tm = 0; tm < 4; tm++)
#pragma unroll
        for (int tn = 0; tn < 4; tn++) {
            const int row = m0 + wm * 64 + tm * 16 + g;
            const int col = n0 + wn * 32 + tn * 8 + 2 * qd;
            const float bv0 = bias[col], bv1 = bias[col + 1];
            *(float2*)&C[(size_t)row * HID + col] =
                make_float2(acc[tm][tn][0] + bv0, acc[tm][tn][1] + bv1);
            *(float2*)&C[(size_t)(row + 8) * HID + col] =
                make_float2(acc[tm][tn][2] + bv0, acc[tm][tn][3] + bv1);
        }
}

#define QSTRIDE 72   // 64 + 8 pad

// ============== score: S = (q.k + q.pk_band + k.pq_band)/sqrt(192) ===========
__global__ __launch_bounds__(256)
void score_mma()
{
    extern __shared__ char smraw[];
    __nv_bfloat16* qS = (__nv_bfloat16*)smraw;         // [128][72]
    __nv_bfloat16* kS = qS + 128 * QSTRIDE;            // [128][72]
    __nv_bfloat16* bS = kS + 128 * QSTRIDE;            // [256][72]
    float*         Gs = (float*)(bS + 256 * QSTRIDE);  // [128][132]

    const int h = blockIdx.z, i0 = blockIdx.y * 128, j0 = blockIdx.x * 128;
    const int t = threadIdx.x, lane = t & 31, warp = t >> 5;
    const int g = lane >> 2, qd = lane & 3;
    const int wm = warp >> 2, wn = warp & 3;

    // stage q, k as bf16
    {
        const int lrow = t >> 1, dh = (t & 1) * 32;
        const float* qp = g_q + (size_t)(i0 + lrow) * HID + h * DHEAD + dh;
        const float* kp = g_k + (size_t)(j0 + lrow) * HID + h * DHEAD + dh;
        uint32_t uq[16], uk[16];
#pragma unroll
        for (int f = 0; f < 8; f++) {
            float4 a = *(const float4*)(qp + f * 4);
            float4 b = *(const float4*)(kp + f * 4);
            uq[f*2] = f2bf2(a.x, a.y); uq[f*2+1] = f2bf2(a.z, a.w);
            uk[f*2] = f2bf2(b.x, b.y); uk[f*2+1] = f2bf2(b.z, b.w);
        }
        uint32_t* dq = (uint32_t*)&qS[lrow * QSTRIDE + dh];
        uint32_t* dk = (uint32_t*)&kS[lrow * QSTRIDE + dh];
#pragma unroll
        for (int f = 0; f < 4; f++) {
            *(uint4*)(dq + f * 4) = make_uint4(uq[f*4], uq[f*4+1], uq[f*4+2], uq[f*4+3]);
            *(uint4*)(dk + f * 4) = make_uint4(uk[f*4], uk[f*4+1], uk[f*4+2], uk[f*4+3]);
        }
    }
    const int dmin = 1024 + i0 - j0 - 127;
    {
        const int brow = (t < 255) ? t : 254;
        const float* bp = g_pk + (size_t)(dmin + brow) * HID + h * DHEAD;
        uint32_t ub[32];
#pragma unroll
        for (int f = 0; f < 16; f++) {
            float4 a = *(const float4*)(bp + f * 4);
            ub[f*2] = f2bf2(a.x, a.y); ub[f*2+1] = f2bf2(a.z, a.w);
        }
        uint32_t* db = (uint32_t*)&bS[t * QSTRIDE];
#pragma unroll
        for (int f = 0; f < 8; f++)
            *(uint4*)(db + f * 4) = make_uint4(ub[f*4], ub[f*4+1], ub[f*4+2], ub[f*4+3]);
    }
    __syncthreads();

    float S[4][4][4];
#pragma unroll
    for (int i = 0; i < 4; i++)
#pragma unroll
        for (int j = 0; j < 4; j++)
#pragma unroll
            for (int e = 0; e < 4; e++) S[i][j][e] = 0.0f;

    // QK
#pragma unroll
    for (int kk = 0; kk < 4; kk++) {
        uint32_t af[4][4], bf[4][2];
#pragma unroll
        for (int tm = 0; tm < 4; tm++) {
            const int row = wm * 64 + tm * 16 + g;
            af[tm][0] = *(const uint32_t*)&qS[row * QSTRIDE + kk * 16 + 2 * qd];
            af[tm][1] = *(const uint32_t*)&qS[(row + 8) * QSTRIDE + kk * 16 + 2 * qd];
            af[tm][2] = *(const uint32_t*)&qS[row * QSTRIDE + kk * 16 + 2 * qd + 8];
            af[tm][3] = *(const uint32_t*)&qS[(row + 8) * QSTRIDE + kk * 16 + 2 * qd + 8];
        }
#pragma unroll
        for (int tn = 0; tn < 4; tn++) {
            const int col = wn * 32 + tn * 8 + g;
            bf[tn][0] = *(const uint32_t*)&kS[col * QSTRIDE + kk * 16 + 2 * qd];
            bf[tn][1] = *(const uint32_t*)&kS[col * QSTRIDE + kk * 16 + 2 * qd + 8];
        }
#pragma unroll
        for (int tm = 0; tm < 4; tm++)
#pragma unroll
            for (int tn = 0; tn < 4; tn++) mma16(S[tm][tn], af[tm], bf[tn]);
    }

    // position passes: pass 0 = c2p (q x pk_band), pass 1 = p2c (k x pq_band)
    for (int pass = 0; pass < 2; pass++) {
        if (pass == 1) {
            const int brow = (t < 255) ? t : 254;
            const float* bp = g_pq + (size_t)(dmin + brow) * HID + h * DHEAD;
            uint32_t ub[32];
#pragma unroll
            for (int f = 0; f < 16; f++) {
                float4 a = *(const float4*)(bp + f * 4);
                ub[f*2] = f2bf2(a.x, a.y); ub[f*2+1] = f2bf2(a.z, a.w);
            }
            uint32_t* db = (uint32_t*)&bS[t * QSTRIDE];
#pragma unroll
            for (int f = 0; f < 8; f++)
                *(uint4*)(db + f * 4) = make_uint4(ub[f*4], ub[f*4+1], ub[f*4+2], ub[f*4+3]);
            __syncthreads();
        }
        const __nv_bfloat16* X = (pass == 0) ? qS : kS;
        for (int bh = 0; bh < 2; bh++) {
            float Ga[4][4][4];
#pragma unroll
            for (int i = 0; i < 4; i++)
#pragma unroll
                for (int j = 0; j < 4; j++)
#pragma unroll
                    for (int e = 0; e < 4; e++) Ga[i][j][e] = 0.0f;
#pragma unroll
            for (int kk = 0; kk < 4; kk++) {
                uint32_t af[4][4], bf[4][2];
#pragma unroll
                for (int tm = 0; tm < 4; tm++) {
                    const int row = wm * 64 + tm * 16 + g;
                    af[tm][0] = *(const uint32_t*)&X[row * QSTRIDE + kk * 16 + 2 * qd];
                    af[tm][1] = *(const uint32_t*)&X[(row + 8) * QSTRIDE + kk * 16 + 2 * qd];
                    af[tm][2] = *(const uint32_t*)&X[row * QSTRIDE + kk * 16 + 2 * qd + 8];
                    af[tm][3] = *(const uint32_t*)&X[(row + 8) * QSTRIDE + kk * 16 + 2 * qd + 8];
                }
#pragma unroll
                for (int tn = 0; tn < 4; tn++) {
                    const int b = bh * 128 + wn * 32 + tn * 8 + g;
                    bf[tn][0] = *(const uint32_t*)&bS[b * QSTRIDE + kk * 16 + 2 * qd];
                    bf[tn][1] = *(const uint32_t*)&bS[b * QSTRIDE + kk * 16 + 2 * qd + 8];
                }
#pragma unroll
                for (int tm = 0; tm < 4; tm++)
#pragma unroll
                    for (int tn = 0; tn < 4; tn++) mma16(Ga[tm][tn], af[tm], bf[tn]);
            }
            // store G half to smem
#pragma unroll
            for (int tm = 0; tm < 4; tm++)
#pragma unroll
                for (int tn = 0; tn < 4; tn++) {
                    const int r = wm * 64 + tm * 16 + g;
                    const int c = wn * 32 + tn * 8 + 2 * qd;
                    *(float2*)&Gs[r * 132 + c] = make_float2(Ga[tm][tn][0], Ga[tm][tn][1]);
                    *(float2*)&Gs[(r + 8) * 132 + c] = make_float2(Ga[tm][tn][2], Ga[tm][tn][3]);
                }
            __syncthreads();
            // gather band contributions into S
#pragma unroll
            for (int tm = 0; tm < 4; tm++)
#pragma unroll
                for (int tn = 0; tn < 4; tn++) {
                    const int il = wm * 64 + tm * 16 + g;
                    const int jl = wn * 32 + tn * 8 + 2 * qd;
                    const int b0v = il - jl + 127 - bh * 128;
                    const int bv[4] = {b0v, b0v - 1, b0v + 8, b0v + 7};
                    int rv[4];
                    if (pass == 0) { rv[0] = il; rv[1] = il; rv[2] = il + 8; rv[3] = il + 8; }
                    else           { rv[0] = jl; rv[1] = jl + 1; rv[2] = jl; rv[3] = jl + 1; }
#pragma unroll
                    for (int e = 0; e < 4; e++)
                        if ((unsigned)bv[e] < 128u)
                            S[tm][tn][e] += Gs[rv[e] * 132 + bv[e]];
                }
            __syncthreads();
        }
    }

    const float inv = 0.07216878364870322992f;  // 1/sqrt(192)
#pragma unroll
    for (int tm = 0; tm < 4; tm++)
#pragma unroll
        for (int tn = 0; tn < 4; tn++) {
            const int row = i0 + wm * 64 + tm * 16 + g;
            const int col = j0 + wn * 32 + tn * 8 + 2 * qd;
            float* o0 = g_scores + ((size_t)h * NSEQ + row) * NSEQ + col;
            float* o1 = g_scores + ((size_t)h * NSEQ + row + 8) * NSEQ + col;
            *(float2*)o0 = make_float2(S[tm][tn][0] * inv, S[tm][tn][1] * inv);
            *(float2*)o1 = make_float2(S[tm][tn][2] * inv, S[tm][tn][3] * inv);
        }
}

// ============== stats: one warp per (h,i) row ================================
__global__ __launch_bounds__(256)
void stats_kernel()
{
    const int w = (blockIdx.x * 256 + threadIdx.x) >> 5;
    const int lane = threadIdx.x & 31;
    const float* row = g_scores + (size_t)w * NSEQ;
    float v[32];
#pragma unroll
    for (int c = 0; c < 8; c++) {
        float4 x = *(const float4*)(row + c * 128 + lane * 4);
        v[c*4+0]=x.x; v[c*4+1]=x.y; v[c*4+2]=x.z; v[c*4+3]=x.w;
    }
    float m = v[0];
#pragma unroll
    for (int i = 1; i < 32; i++) m = fmaxf(m, v[i]);
#pragma unroll
    for (int o = 16; o > 0; o >>= 1) m = fmaxf(m, __shfl_xor_sync(0xffffffffu, m, o));
    float s = 0.0f;
#pragma unroll
    for (int i = 0; i < 32; i++) s += __expf(v[i] - m);
#pragma unroll
    for (int o = 16; o > 0; o >>= 1) s += __shfl_xor_sync(0xffffffffu, s, o);
    if (lane == 0) { g_rmax[w] = m; g_rinv[w] = 1.0f / s; }
}

#define PSTRIDE 40  // 32 + 8 pad

// ============== AV: ctx = softmax(S) @ V via bf16 mma ========================
__global__ __launch_bounds__(256)
void av_mma()
{
    __shared__ __nv_bfloat16 Ps[128 * PSTRIDE];  // [i][j]
    __shared__ __nv_bfloat16 Vt[64 * PSTRIDE];   // [d][j]
    const int h = blockIdx.y, i0 = blockIdx.x * 128;
    const int t = threadIdx.x, lane = t & 31, warp = t >> 5;
    const int g = lane >> 2, qd = lane & 3;
    const int wm = warp >> 2, wn = warp & 3;

    const int lrow = t >> 1, lj = (t & 1) * 16;
    const float m  = g_rmax[h * NSEQ + i0 + lrow];
    const float ri = g_rinv[h * NSEQ + i0 + lrow];

    float acc[4][2][4];
#pragma unroll
    for (int i = 0; i < 4; i++)
#pragma unroll
        for (int j = 0; j < 2; j++)
#pragma unroll
            for (int e = 0; e < 4; e++) acc[i][j][e] = 0.0f;

    for (int jt = 0; jt < NSEQ; jt += 32) {
        __syncthreads();
        // stage P = exp(S - m) * ri  (bf16)
        {
            const float* sp = g_scores + ((size_t)h * NSEQ + i0 + lrow) * NSEQ + jt + lj;
            uint32_t up[8];
#pragma unroll
            for (int f = 0; f < 4; f++) {
                float4 x = *(const float4*)(sp + f * 4);
                up[f*2]   = f2bf2(__expf(x.x - m) * ri, __expf(x.y - m) * ri);
                up[f*2+1] = f2bf2(__expf(x.z - m) * ri, __expf(x.w - m) * ri);
            }
            uint32_t* dp = (uint32_t*)&Ps[lrow * PSTRIDE + lj];
            *(uint4*)dp       = make_uint4(up[0], up[1], up[2], up[3]);
            *(uint4*)(dp + 4) = make_uint4(up[4], up[5], up[6], up[7]);
        }
        // stage V transposed: Vt[d][j]
        {
            const int vr = t >> 3, dblk = (t & 7) * 8;
            const float* vp = g_v + (size_t)(jt + vr) * HID + h * DHEAD + dblk;
            float4 a = *(const float4*)vp;
            float4 b = *(const float4*)(vp + 4);
            Vt[(dblk + 0) * PSTRIDE + vr] = __float2bfloat16(a.x);
            Vt[(dblk + 1) * PSTRIDE + vr] = __float2bfloat16(a.y);
            Vt[(dblk + 2) * PSTRIDE + vr] = __float2bfloat16(a.z);
            Vt[(dblk + 3) * PSTRIDE + vr] = __float2bfloat16(a.w);
            Vt[(dblk + 4) * PSTRIDE + vr] = __float2bfloat16(b.x);
            Vt[(dblk + 5) * PSTRIDE + vr] = __float2bfloat16(b.y);
            Vt[(dblk + 6) * PSTRIDE + vr] = __float2bfloat16(b.z);
            Vt[(dblk + 7) * PSTRIDE + vr] = __float2bfloat16(b.w);
        }
        __syncthreads();
#pragma unroll
        for (int kk = 0; kk < 2; kk++) {
            uint32_t af[4][4], bf[2][2];
#pragma unroll
            for (int tm = 0; tm < 4; tm++) {
                const int row = wm * 64 + tm * 16 + g;
                af[tm][0] = *(const uint32_t*)&Ps[row * PSTRIDE + kk * 16 + 2 * qd];
                af[tm][1] = *(const uint32_t*)&Ps[(row + 8) * PSTRIDE + kk * 16 + 2 * qd];
                af[tm][2] = *(const uint32_t*)&Ps[row * PSTRIDE + kk * 16 + 2 * qd + 8];
                af[tm][3] = *(const uint32_t*)&Ps[(row + 8) * PSTRIDE + kk * 16 + 2 * qd + 8];
            }
#pragma unroll
            for (int tn = 0; tn < 2; tn++) {
                const int col = wn * 16 + tn * 8 + g;
                bf[tn][0] = *(const uint32_t*)&Vt[col * PSTRIDE + kk * 16 + 2 * qd];
                bf[tn][1] = *(const uint32_t*)&Vt[col * PSTRIDE + kk * 16 + 2 * qd + 8];
            }
#pragma unroll
            for (int tm = 0; tm < 4; tm++)
#pragma unroll
                for (int tn = 0; tn < 2; tn++) mma16(acc[tm][tn], af[tm], bf[tn]);
        }
    }
#pragma unroll
    for (int tm = 0; tm < 4; tm++)
#pragma unroll
        for (int tn = 0; tn < 2; tn++) {
            const int row = i0 + wm * 64 + tm * 16 + g;
            const int col = h * DHEAD + wn * 16 + tn * 8 + 2 * qd;
            *(float2*)&g_ctx[(size_t)row * HID + col] =
                make_float2(acc[tm][tn][0], acc[tm][tn][1]);
            *(float2*)&g_ctx[(size_t)(row + 8) * HID + col] =
                make_float2(acc[tm][tn][2], acc[tm][tn][3]);
        }
}

// ============== residual + LayerNorm =========================================
__global__ __launch_bounds__(256)
void ln_kernel(const float* __restrict__ hs, const float* __restrict__ gg,
               const float* __restrict__ bb, float* __restrict__ out)
{
    const int row = blockIdx.x, t = threadIdx.x;
    __shared__ float red[8];
    float4 p = *(const float4*)(g_proj + (size_t)row * HID + t * 4);
    float4 hv = *(const float4*)(hs + (size_t)row * HID + t * 4);
    float x0 = p.x+hv.x, x1 = p.y+hv.y, x2 = p.z+hv.z, x3 = p.w+hv.w;
    float s = x0+x1+x2+x3;
#pragma unroll
    for (int o = 16; o > 0; o >>= 1) s += __shfl_xor_sync(0xffffffffu, s, o);
    if ((t & 31) == 0) red[t >> 5] = s;
    __syncthreads();
    float mu = (red[0]+red[1]+red[2]+red[3]+red[4]+red[5]+red[6]+red[7]) * (1.0f/1024.0f);
    float d0 = x0-mu, d1 = x1-mu, d2 = x2-mu, d3 = x3-mu;
    float sq = d0*d0 + d1*d1 + d2*d2 + d3*d3;
#pragma unroll
    for (int o = 16; o > 0; o >>= 1) sq += __shfl_xor_sync(0xffffffffu, sq, o);
    __syncthreads();
    if ((t & 31) == 0) red[t >> 5] = sq;
    __syncthreads();
    float var = (red[0]+red[1]+red[2]+red[3]+red[4]+red[5]+red[6]+red[7]) * (1.0f/1024.0f);
    float rstd = rsqrtf(var + 1e-7f);
    float4 g4 = *(const float4*)(gg + t * 4);
    float4 b4 = *(const float4*)(bb + t * 4);
    *(float4*)(out + (size_t)row * HID + t * 4) =
        make_float4(d0*rstd*g4.x + b4.x, d1*rstd*g4.y + b4.y,
                    d2*rstd*g4.z + b4.z, d3*rstd*g4.w + b4.w);
}

extern "C" void kernel_launch(void* const* d_in, const int* in_sizes, int n_in,
                              void* d_out, int out_size)
{
    const float* hs  = (const float*)d_in[0];
    const float* rel = (const float*)d_in[1];
    const float* Wq  = (const float*)d_in[2];  const float* bq  = (const float*)d_in[3];
    const float* Wk  = (const float*)d_in[4];  const float* bk  = (const float*)d_in[5];
    const float* Wv  = (const float*)d_in[6];  const float* bv  = (const float*)d_in[7];
    const float* Wpk = (const float*)d_in[8];  const float* bpk = (const float*)d_in[9];
    const float* Wpq = (const float*)d_in[10]; const float* bpq = (const float*)d_in[11];
    const float* Wo  = (const float*)d_in[12]; const float* bo  = (const float*)d_in[13];
    const float* lng = (const float*)d_in[14]; const float* lnb = (const float*)d_in[15];

    float *q_, *k_, *v_, *pk_, *pq_, *ctx_, *proj_;
    cudaGetSymbolAddress((void**)&q_, g_q);
    cudaGetSymbolAddress((void**)&k_, g_k);
    cudaGetSymbolAddress((void**)&v_, g_v);
    cudaGetSymbolAddress((void**)&pk_, g_pk);
    cudaGetSymbolAddress((void**)&pq_, g_pq);
    cudaGetSymbolAddress((void**)&ctx_, g_ctx);
    cudaGetSymbolAddress((void**)&proj_, g_proj);

    const int score_smem = (2 * 128 * QSTRIDE + 256 * QSTRIDE) * 2 + 128 * 132 * 4;
    cudaFuncSetAttribute(score_mma, cudaFuncAttributeMaxDynamicSharedMemorySize, score_smem);

    gemm_bf16<<<dim3(8, 8, 3), 256>>>(hs, Wq, bq, q_, Wk, bk, k_, Wv, bv, v_);
    gemm_bf16<<<dim3(8, 16, 2), 256>>>(rel, Wpk, bpk, pk_, Wpq, bpq, pq_, Wpq, bpq, pq_);
    score_mma<<<dim3(8, 8, 16), 256, score_smem>>>();
    stats_kernel<<<2048, 256>>>();
    av_mma<<<dim3(8, 16), 256>>>();
    gemm_bf16<<<dim3(8, 8, 1), 256>>>(ctx_, Wo, bo, proj_, Wo, bo, proj_, Wo, bo, proj_);
    ln_kernel<<<1024, 256>>>(hs, lng, lnb, (float*)d_out);
}

// round 6
// speedup vs baseline: 2.5945x; 1.0546x over previous
#include <cuda_runtime.h>
#include <cuda_bf16.h>
#include <stdint.h>

#define HID   1024
#define NSEQ  1024
#define DHEAD 64

__device__ float g_q[NSEQ * HID];
__device__ float g_k[NSEQ * HID];
__device__ float g_v[NSEQ * HID];
__device__ float g_pk[2048 * HID];
__device__ float g_pq[2048 * HID];
__device__ float g_scores[16 * NSEQ * NSEQ];   // holds exp(S) after score pass
__device__ float g_psum[16 * NSEQ * 8];        // per-row partial exp-sums, 8 j-blocks
__device__ float g_ctx[NSEQ * HID];
__device__ float g_proj[NSEQ * HID];

__device__ __forceinline__ uint32_t f2bf2(float lo, float hi) {
    uint32_t r;
    asm("cvt.rn.bf16x2.f32 %0, %1, %2;" : "=r"(r) : "f"(hi), "f"(lo));
    return r;
}
__device__ __forceinline__ void mma16(float* c, const uint32_t* a, const uint32_t* b) {
    asm volatile(
        "mma.sync.aligned.m16n8k16.row.col.f32.bf16.bf16.f32 "
        "{%0,%1,%2,%3}, {%4,%5,%6,%7}, {%8,%9}, {%0,%1,%2,%3};\n"
        : "+f"(c[0]), "+f"(c[1]), "+f"(c[2]), "+f"(c[3])
        : "r"(a[0]), "r"(a[1]), "r"(a[2]), "r"(a[3]), "r"(b[0]), "r"(b[1]));
}
__device__ __forceinline__ void ldsm4(uint32_t* r, uint32_t addr) {
    asm volatile("ldmatrix.sync.aligned.m8n8.x4.shared.b16 {%0,%1,%2,%3}, [%4];\n"
        : "=r"(r[0]), "=r"(r[1]), "=r"(r[2]), "=r"(r[3]) : "r"(addr));
}
__device__ __forceinline__ uint32_t smem_u32(const void* p) {
    return (uint32_t)__cvta_generic_to_shared(p);
}

#define ASTRIDE 40   // 32 K + 8 pad (bf16)

// ============== bf16 NT GEMM, ldmatrix fragments ==============
__global__ __launch_bounds__(256)
void gemm_bf16(const float* __restrict__ A,
               const float* __restrict__ W0, const float* __restrict__ b0, float* __restrict__ C0,
               const float* __restrict__ W1, const float* __restrict__ b1, float* __restrict__ C1,
               const float* __restrict__ W2, const float* __restrict__ b2, float* __restrict__ C2)
{
    __shared__ __nv_bfloat16 As[2][128 * ASTRIDE];
    __shared__ __nv_bfloat16 Ws[2][128 * ASTRIDE];

    const int z = blockIdx.z;
    const float* W    = (z == 0) ? W0 : ((z == 1) ? W1 : W2);
    const float* bias = (z == 0) ? b0 : ((z == 1) ? b1 : b2);
    float*       C    = (z == 0) ? C0 : ((z == 1) ? C1 : C2);

    const int m0 = blockIdx.y * 128, n0 = blockIdx.x * 128;
    const int t = threadIdx.x, lane = t & 31, warp = t >> 5;
    const int g = lane >> 2, qd = lane & 3;
    const int wm = warp >> 2, wn = warp & 3;
    const int lr7 = lane & 7;

    // ldmatrix lane offsets (bytes)
    const uint32_t aoff = ((uint32_t)((wm * 64 + lr7 + ((lane >> 3) & 1) * 8) * ASTRIDE
                          + (lane >> 4) * 8)) * 2;
    const uint32_t boff = ((uint32_t)((wn * 32 + lr7 + (lane >> 4) * 8) * ASTRIDE
                          + ((lane >> 3) & 1) * 8)) * 2;
    const uint32_t asb = smem_u32(As[0]);
    const uint32_t wsb = smem_u32(Ws[0]);
    const uint32_t bufstep = 128 * ASTRIDE * 2;

    const int lrow = t >> 1, lkoff = (t & 1) * 16;
    const float* Ap = A + (size_t)(m0 + lrow) * HID + lkoff;
    const float* Wp = W + (size_t)(n0 + lrow) * HID + lkoff;

    {
        uint32_t pa[8], pw[8];
#pragma unroll
        for (int f = 0; f < 4; f++) {
            float4 va = *(const float4*)(Ap + f * 4);
            float4 vw = *(const float4*)(Wp + f * 4);
            pa[f*2] = f2bf2(va.x, va.y); pa[f*2+1] = f2bf2(va.z, va.w);
            pw[f*2] = f2bf2(vw.x, vw.y); pw[f*2+1] = f2bf2(vw.z, vw.w);
        }
        uint32_t* da = (uint32_t*)&As[0][lrow * ASTRIDE + lkoff];
        uint32_t* dw = (uint32_t*)&Ws[0][lrow * ASTRIDE + lkoff];
        *(uint4*)da = make_uint4(pa[0], pa[1], pa[2], pa[3]);
        *(uint4*)(da + 4) = make_uint4(pa[4], pa[5], pa[6], pa[7]);
        *(uint4*)dw = make_uint4(pw[0], pw[1], pw[2], pw[3]);
        *(uint4*)(dw + 4) = make_uint4(pw[4], pw[5], pw[6], pw[7]);
    }
    __syncthreads();

    float acc[4][4][4];
#pragma unroll
    for (int i = 0; i < 4; i++)
#pragma unroll
        for (int j = 0; j < 4; j++)
#pragma unroll
            for (int e = 0; e < 4; e++) acc[i][j][e] = 0.0f;

    for (int kt = 0; kt < 32; kt++) {
        const int cur = kt & 1;
        float4 pa4[4], pw4[4];
        const bool more = (kt + 1 < 32);
        if (more) {
#pragma unroll
            for (int f = 0; f < 4; f++) {
                pa4[f] = *(const float4*)(Ap + (kt + 1) * 32 + f * 4);
                pw4[f] = *(const float4*)(Wp + (kt + 1) * 32 + f * 4);
            }
        }
        const uint32_t Abase = asb + cur * bufstep + aoff;
        const uint32_t Bbase = wsb + cur * bufstep + boff;
#pragma unroll
        for (int kk = 0; kk < 2; kk++) {
            uint32_t af[4][4], bf[4][2];
#pragma unroll
            for (int tm = 0; tm < 4; tm++)
                ldsm4(af[tm], Abase + tm * 16 * ASTRIDE * 2 + kk * 32);
#pragma unroll
            for (int tnp = 0; tnp < 2; tnp++) {
                uint32_t bb[4];
                ldsm4(bb, Bbase + tnp * 16 * ASTRIDE * 2 + kk * 32);
                bf[2*tnp][0] = bb[0]; bf[2*tnp][1] = bb[1];
                bf[2*tnp+1][0] = bb[2]; bf[2*tnp+1][1] = bb[3];
            }
#pragma unroll
            for (int tm = 0; tm < 4; tm++)
#pragma unroll
                for (int tn = 0; tn < 4; tn++) mma16(acc[tm][tn], af[tm], bf[tn]);
        }
        if (more) {
            const int nx = cur ^ 1;
            uint32_t qa[8], qw[8];
#pragma unroll
            for (int f = 0; f < 4; f++) {
                qa[f*2] = f2bf2(pa4[f].x, pa4[f].y); qa[f*2+1] = f2bf2(pa4[f].z, pa4[f].w);
                qw[f*2] = f2bf2(pw4[f].x, pw4[f].y); qw[f*2+1] = f2bf2(pw4[f].z, pw4[f].w);
            }
            uint32_t* da = (uint32_t*)&As[nx][lrow * ASTRIDE + lkoff];
            uint32_t* dw = (uint32_t*)&Ws[nx][lrow * ASTRIDE + lkoff];
            *(uint4*)da = make_uint4(qa[0], qa[1], qa[2], qa[3]);
            *(uint4*)(da + 4) = make_uint4(qa[4], qa[5], qa[6], qa[7]);
            *(uint4*)dw = make_uint4(qw[0], qw[1], qw[2], qw[3]);
            *(uint4*)(dw + 4) = make_uint4(qw[4], qw[5], qw[6], qw[7]);
            __syncthreads();
        }
    }

#pragma unroll
    for (int tm = 0; tm < 4; tm++)
#pragma unroll
        for (int tn = 0; tn < 4; tn++) {
            const int row = m0 + wm * 64 + tm * 16 + g;
            const int col = n0 + wn * 32 + tn * 8 + 2 * qd;
            const float bv0 = bias[col], bv1 = bias[col + 1];
            *(float2*)&C[(size_t)row * HID + col] =
                make_float2(acc[tm][tn][0] + bv0, acc[tm][tn][1] + bv1);
            *(float2*)&C[(size_t)(row + 8) * HID + col] =
                make_float2(acc[tm][tn][2] + bv0, acc[tm][tn][3] + bv1);
        }
}

#define QSTRIDE 72   // 64 + 8 pad

// ===== score: writes exp((qk + c2p + p2c)/sqrt(192)) and per-row partial sums =====
__global__ __launch_bounds__(256)
void score_mma()
{
    extern __shared__ char smraw[];
    __nv_bfloat16* qS = (__nv_bfloat16*)smraw;         // [128][72]
    __nv_bfloat16* kS = qS + 128 * QSTRIDE;            // [128][72]
    __nv_bfloat16* bS = kS + 128 * QSTRIDE;            // [256][72]
    float*         Gs = (float*)(bS + 256 * QSTRIDE);  // [128][132]

    const int h = blockIdx.z, i0 = blockIdx.y * 128, j0 = blockIdx.x * 128;
    const int t = threadIdx.x, lane = t & 31, warp = t >> 5;
    const int g = lane >> 2, qd = lane & 3;
    const int wm = warp >> 2, wn = warp & 3;
    const int lr7 = lane & 7;

    const uint32_t aoffQ = ((uint32_t)((wm * 64 + lr7 + ((lane >> 3) & 1) * 8) * QSTRIDE
                           + (lane >> 4) * 8)) * 2;
    const uint32_t boffQ = ((uint32_t)((wn * 32 + lr7 + (lane >> 4) * 8) * QSTRIDE
                           + ((lane >> 3) & 1) * 8)) * 2;
    const uint32_t qSb = smem_u32(qS), kSb = smem_u32(kS), bSb = smem_u32(bS);

    // stage q, k
    {
        const int lrow = t >> 1, dh = (t & 1) * 32;
        const float* qp = g_q + (size_t)(i0 + lrow) * HID + h * DHEAD + dh;
        const float* kp = g_k + (size_t)(j0 + lrow) * HID + h * DHEAD + dh;
        uint32_t uq[16], uk[16];
#pragma unroll
        for (int f = 0; f < 8; f++) {
            float4 a = *(const float4*)(qp + f * 4);
            float4 b = *(const float4*)(kp + f * 4);
            uq[f*2] = f2bf2(a.x, a.y); uq[f*2+1] = f2bf2(a.z, a.w);
            uk[f*2] = f2bf2(b.x, b.y); uk[f*2+1] = f2bf2(b.z, b.w);
        }
        uint32_t* dq = (uint32_t*)&qS[lrow * QSTRIDE + dh];
        uint32_t* dk = (uint32_t*)&kS[lrow * QSTRIDE + dh];
#pragma unroll
        for (int f = 0; f < 4; f++) {
            *(uint4*)(dq + f * 4) = make_uint4(uq[f*4], uq[f*4+1], uq[f*4+2], uq[f*4+3]);
            *(uint4*)(dk + f * 4) = make_uint4(uk[f*4], uk[f*4+1], uk[f*4+2], uk[f*4+3]);
        }
    }
    const int dmin = 1024 + i0 - j0 - 127;
    {
        const int brow = (t < 255) ? t : 254;
        const float* bp = g_pk + (size_t)(dmin + brow) * HID + h * DHEAD;
        uint32_t ub[32];
#pragma unroll
        for (int f = 0; f < 16; f++) {
            float4 a = *(const float4*)(bp + f * 4);
            ub[f*2] = f2bf2(a.x, a.y); ub[f*2+1] = f2bf2(a.z, a.w);
        }
        uint32_t* db = (uint32_t*)&bS[t * QSTRIDE];
#pragma unroll
        for (int f = 0; f < 8; f++)
            *(uint4*)(db + f * 4) = make_uint4(ub[f*4], ub[f*4+1], ub[f*4+2], ub[f*4+3]);
    }
    __syncthreads();

    float S[4][4][4];
#pragma unroll
    for (int i = 0; i < 4; i++)
#pragma unroll
        for (int j = 0; j < 4; j++)
#pragma unroll
            for (int e = 0; e < 4; e++) S[i][j][e] = 0.0f;

    // QK
#pragma unroll
    for (int kk = 0; kk < 4; kk++) {
        uint32_t af[4][4], bf[4][2];
#pragma unroll
        for (int tm = 0; tm < 4; tm++)
            ldsm4(af[tm], qSb + aoffQ + tm * 16 * QSTRIDE * 2 + kk * 32);
#pragma unroll
        for (int tnp = 0; tnp < 2; tnp++) {
            uint32_t bb[4];
            ldsm4(bb, kSb + boffQ + tnp * 16 * QSTRIDE * 2 + kk * 32);
            bf[2*tnp][0] = bb[0]; bf[2*tnp][1] = bb[1];
            bf[2*tnp+1][0] = bb[2]; bf[2*tnp+1][1] = bb[3];
        }
#pragma unroll
        for (int tm = 0; tm < 4; tm++)
#pragma unroll
            for (int tn = 0; tn < 4; tn++) mma16(S[tm][tn], af[tm], bf[tn]);
    }

    // band passes: pass 0 = c2p (q x pk_band), pass 1 = p2c (k x pq_band)
    for (int pass = 0; pass < 2; pass++) {
        if (pass == 1) {
            const int brow = (t < 255) ? t : 254;
            const float* bp = g_pq + (size_t)(dmin + brow) * HID + h * DHEAD;
            uint32_t ub[32];
#pragma unroll
            for (int f = 0; f < 16; f++) {
                float4 a = *(const float4*)(bp + f * 4);
                ub[f*2] = f2bf2(a.x, a.y); ub[f*2+1] = f2bf2(a.z, a.w);
            }
            uint32_t* db = (uint32_t*)&bS[t * QSTRIDE];
#pragma unroll
            for (int f = 0; f < 8; f++)
                *(uint4*)(db + f * 4) = make_uint4(ub[f*4], ub[f*4+1], ub[f*4+2], ub[f*4+3]);
            __syncthreads();
        }
        const uint32_t Xb = (pass == 0) ? qSb : kSb;
        for (int bh = 0; bh < 2; bh++) {
            float Ga[4][4][4];
#pragma unroll
            for (int i = 0; i < 4; i++)
#pragma unroll
                for (int j = 0; j < 4; j++)
#pragma unroll
                    for (int e = 0; e < 4; e++) Ga[i][j][e] = 0.0f;
#pragma unroll
            for (int kk = 0; kk < 4; kk++) {
                uint32_t af[4][4], bf[4][2];
#pragma unroll
                for (int tm = 0; tm < 4; tm++)
                    ldsm4(af[tm], Xb + aoffQ + tm * 16 * QSTRIDE * 2 + kk * 32);
#pragma unroll
                for (int tnp = 0; tnp < 2; tnp++) {
                    uint32_t bb[4];
                    ldsm4(bb, bSb + boffQ + (bh * 128 + tnp * 16) * QSTRIDE * 2 + kk * 32);
                    bf[2*tnp][0] = bb[0]; bf[2*tnp][1] = bb[1];
                    bf[2*tnp+1][0] = bb[2]; bf[2*tnp+1][1] = bb[3];
                }
#pragma unroll
                for (int tm = 0; tm < 4; tm++)
#pragma unroll
                    for (int tn = 0; tn < 4; tn++) mma16(Ga[tm][tn], af[tm], bf[tn]);
            }
#pragma unroll
            for (int tm = 0; tm < 4; tm++)
#pragma unroll
                for (int tn = 0; tn < 4; tn++) {
                    const int r = wm * 64 + tm * 16 + g;
                    const int c = wn * 32 + tn * 8 + 2 * qd;
                    *(float2*)&Gs[r * 132 + c] = make_float2(Ga[tm][tn][0], Ga[tm][tn][1]);
                    *(float2*)&Gs[(r + 8) * 132 + c] = make_float2(Ga[tm][tn][2], Ga[tm][tn][3]);
                }
            __syncthreads();
#pragma unroll
            for (int tm = 0; tm < 4; tm++)
#pragma unroll
                for (int tn = 0; tn < 4; tn++) {
                    const int il = wm * 64 + tm * 16 + g;
                    const int jl = wn * 32 + tn * 8 + 2 * qd;
                    const int b0v = il - jl + 127 - bh * 128;
                    const int bv[4] = {b0v, b0v - 1, b0v + 8, b0v + 7};
                    int rv[4];
                    if (pass == 0) { rv[0] = il; rv[1] = il; rv[2] = il + 8; rv[3] = il + 8; }
                    else           { rv[0] = jl; rv[1] = jl + 1; rv[2] = jl; rv[3] = jl + 1; }
#pragma unroll
                    for (int e = 0; e < 4; e++)
                        if ((unsigned)bv[e] < 128u)
                            S[tm][tn][e] += Gs[rv[e] * 132 + bv[e]];
                }
            __syncthreads();
        }
    }

    // epilogue: store exp(S/sqrt(192)); reduce row partial sums
    const float inv = 0.07216878364870322992f;
    float rs[4][2];
#pragma unroll
    for (int tm = 0; tm < 4; tm++) {
        float s0 = 0.0f, s1 = 0.0f;
        const int row = i0 + wm * 64 + tm * 16 + g;
        const int colb = j0 + wn * 32 + 2 * qd;
#pragma unroll
        for (int tn = 0; tn < 4; tn++) {
            float e0 = __expf(S[tm][tn][0] * inv);
            float e1 = __expf(S[tm][tn][1] * inv);
            float e2 = __expf(S[tm][tn][2] * inv);
            float e3 = __expf(S[tm][tn][3] * inv);
            s0 += e0 + e1; s1 += e2 + e3;
            float* o0 = g_scores + ((size_t)h * NSEQ + row) * NSEQ + colb + tn * 8;
            float* o1 = g_scores + ((size_t)h * NSEQ + row + 8) * NSEQ + colb + tn * 8;
            *(float2*)o0 = make_float2(e0, e1);
            *(float2*)o1 = make_float2(e2, e3);
        }
        rs[tm][0] = s0; rs[tm][1] = s1;
    }
#pragma unroll
    for (int tm = 0; tm < 4; tm++) {
        float s0 = rs[tm][0], s1 = rs[tm][1];
        s0 += __shfl_xor_sync(0xffffffffu, s0, 1);
        s0 += __shfl_xor_sync(0xffffffffu, s0, 2);
        s1 += __shfl_xor_sync(0xffffffffu, s1, 1);
        s1 += __shfl_xor_sync(0xffffffffu, s1, 2);
        if (qd == 0) {
            const int r = wm * 64 + tm * 16 + g;
            Gs[r * 4 + wn] = s0;
            Gs[(r + 8) * 4 + wn] = s1;
        }
    }
    __syncthreads();
    if (t < 128) {
        float tot = Gs[t * 4] + Gs[t * 4 + 1] + Gs[t * 4 + 2] + Gs[t * 4 + 3];
        g_psum[((size_t)(h << 10) + i0 + t) * 8 + blockIdx.x] = tot;
    }
}

#define PSTRIDE 40  // 32 + 8 pad

// ============== AV: ctx = (expS * ri) @ V via bf16 mma + ldmatrix ============
__global__ __launch_bounds__(256)
void av_mma()
{
    __shared__ __nv_bfloat16 Ps[128 * PSTRIDE];
    __shared__ __nv_bfloat16 Vt[64 * PSTRIDE];
    const int h = blockIdx.y, i0 = blockIdx.x * 128;
    const int t = threadIdx.x, lane = t & 31, warp = t >> 5;
    const int g = lane >> 2, qd = lane & 3;
    const int wm = warp >> 2, wn = warp & 3;
    const int lr7 = lane & 7;

    const uint32_t aoffP = ((uint32_t)((wm * 64 + lr7 + ((lane >> 3) & 1) * 8) * PSTRIDE
                           + (lane >> 4) * 8)) * 2;
    const uint32_t boffV = ((uint32_t)((wn * 16 + lr7 + (lane >> 4) * 8) * PSTRIDE
                           + ((lane >> 3) & 1) * 8)) * 2;
    const uint32_t PsB = smem_u32(Ps), VtB = smem_u32(Vt);

    const int lrow = t >> 1, lj = (t & 1) * 16;
    float ri;
    {
        const float* pp = g_psum + ((size_t)(h << 10) + i0 + lrow) * 8;
        float4 p0 = *(const float4*)pp, p1 = *(const float4*)(pp + 4);
        ri = 1.0f / (p0.x + p0.y + p0.z + p0.w + p1.x + p1.y + p1.z + p1.w);
    }

    float acc[4][2][4];
#pragma unroll
    for (int i = 0; i < 4; i++)
#pragma unroll
        for (int j = 0; j < 2; j++)
#pragma unroll
            for (int e = 0; e < 4; e++) acc[i][j][e] = 0.0f;

    for (int jt = 0; jt < NSEQ; jt += 32) {
        __syncthreads();
        {
            const float* sp = g_scores + ((size_t)h * NSEQ + i0 + lrow) * NSEQ + jt + lj;
            uint32_t up[8];
#pragma unroll
            for (int f = 0; f < 4; f++) {
                float4 x = *(const float4*)(sp + f * 4);
                up[f*2]   = f2bf2(x.x * ri, x.y * ri);
                up[f*2+1] = f2bf2(x.z * ri, x.w * ri);
            }
            uint32_t* dp = (uint32_t*)&Ps[lrow * PSTRIDE + lj];
            *(uint4*)dp = make_uint4(up[0], up[1], up[2], up[3]);
            *(uint4*)(dp + 4) = make_uint4(up[4], up[5], up[6], up[7]);
        }
        {
            const int vr = t >> 3, dblk = (t & 7) * 8;
            const float* vp = g_v + (size_t)(jt + vr) * HID + h * DHEAD + dblk;
            float4 a = *(const float4*)vp;
            float4 b = *(const float4*)(vp + 4);
            Vt[(dblk + 0) * PSTRIDE + vr] = __float2bfloat16(a.x);
            Vt[(dblk + 1) * PSTRIDE + vr] = __float2bfloat16(a.y);
            Vt[(dblk + 2) * PSTRIDE + vr] = __float2bfloat16(a.z);
            Vt[(dblk + 3) * PSTRIDE + vr] = __float2bfloat16(a.w);
            Vt[(dblk + 4) * PSTRIDE + vr] = __float2bfloat16(b.x);
            Vt[(dblk + 5) * PSTRIDE + vr] = __float2bfloat16(b.y);
            Vt[(dblk + 6) * PSTRIDE + vr] = __float2bfloat16(b.z);
            Vt[(dblk + 7) * PSTRIDE + vr] = __float2bfloat16(b.w);
        }
        __syncthreads();
#pragma unroll
        for (int kk = 0; kk < 2; kk++) {
            uint32_t af[4][4], bf[2][2];
#pragma unroll
            for (int tm = 0; tm < 4; tm++)
                ldsm4(af[tm], PsB + aoffP + tm * 16 * PSTRIDE * 2 + kk * 32);
            {
                uint32_t bb[4];
                ldsm4(bb, VtB + boffV + kk * 32);
                bf[0][0] = bb[0]; bf[0][1] = bb[1];
                bf[1][0] = bb[2]; bf[1][1] = bb[3];
            }
#pragma unroll
            for (int tm = 0; tm < 4; tm++)
#pragma unroll
                for (int tn = 0; tn < 2; tn++) mma16(acc[tm][tn], af[tm], bf[tn]);
        }
    }
#pragma unroll
    for (int tm = 0; tm < 4; tm++)
#pragma unroll
        for (int tn = 0; tn < 2; tn++) {
            const int row = i0 + wm * 64 + tm * 16 + g;
            const int col = h * DHEAD + wn * 16 + tn * 8 + 2 * qd;
            *(float2*)&g_ctx[(size_t)row * HID + col] =
                make_float2(acc[tm][tn][0], acc[tm][tn][1]);
            *(float2*)&g_ctx[(size_t)(row + 8) * HID + col] =
                make_float2(acc[tm][tn][2], acc[tm][tn][3]);
        }
}

// ============== residual + LayerNorm =========================================
__global__ __launch_bounds__(256)
void ln_kernel(const float* __restrict__ hs, const float* __restrict__ gg,
               const float* __restrict__ bb, float* __restrict__ out)
{
    const int row = blockIdx.x, t = threadIdx.x;
    __shared__ float red[8];
    float4 p = *(const float4*)(g_proj + (size_t)row * HID + t * 4);
    float4 hv = *(const float4*)(hs + (size_t)row * HID + t * 4);
    float x0 = p.x+hv.x, x1 = p.y+hv.y, x2 = p.z+hv.z, x3 = p.w+hv.w;
    float s = x0+x1+x2+x3;
#pragma unroll
    for (int o = 16; o > 0; o >>= 1) s += __shfl_xor_sync(0xffffffffu, s, o);
    if ((t & 31) == 0) red[t >> 5] = s;
    __syncthreads();
    float mu = (red[0]+red[1]+red[2]+red[3]+red[4]+red[5]+red[6]+red[7]) * (1.0f/1024.0f);
    float d0 = x0-mu, d1 = x1-mu, d2 = x2-mu, d3 = x3-mu;
    float sq = d0*d0 + d1*d1 + d2*d2 + d3*d3;
#pragma unroll
    for (int o = 16; o > 0; o >>= 1) sq += __shfl_xor_sync(0xffffffffu, sq, o);
    __syncthreads();
    if ((t & 31) == 0) red[t >> 5] = sq;
    __syncthreads();
    float var = (red[0]+red[1]+red[2]+red[3]+red[4]+red[5]+red[6]+red[7]) * (1.0f/1024.0f);
    float rstd = rsqrtf(var + 1e-7f);
    float4 g4 = *(const float4*)(gg + t * 4);
    float4 b4 = *(const float4*)(bb + t * 4);
    *(float4*)(out + (size_t)row * HID + t * 4) =
        make_float4(d0*rstd*g4.x + b4.x, d1*rstd*g4.y + b4.y,
                    d2*rstd*g4.z + b4.z, d3*rstd*g4.w + b4.w);
}

extern "C" void kernel_launch(void* const* d_in, const int* in_sizes, int n_in,
                              void* d_out, int out_size)
{
    const float* hs  = (const float*)d_in[0];
    const float* rel = (const float*)d_in[1];
    const float* Wq  = (const float*)d_in[2];  const float* bq  = (const float*)d_in[3];
    const float* Wk  = (const float*)d_in[4];  const float* bk  = (const float*)d_in[5];
    const float* Wv  = (const float*)d_in[6];  const float* bv  = (const float*)d_in[7];
    const float* Wpk = (const float*)d_in[8];  const float* bpk = (const float*)d_in[9];
    const float* Wpq = (const float*)d_in[10]; const float* bpq = (const float*)d_in[11];
    const float* Wo  = (const float*)d_in[12]; const float* bo  = (const float*)d_in[13];
    const float* lng = (const float*)d_in[14]; const float* lnb = (const float*)d_in[15];

    float *q_, *k_, *v_, *pk_, *pq_, *ctx_, *proj_;
    cudaGetSymbolAddress((void**)&q_, g_q);
    cudaGetSymbolAddress((void**)&k_, g_k);
    cudaGetSymbolAddress((void**)&v_, g_v);
    cudaGetSymbolAddress((void**)&pk_, g_pk);
    cudaGetSymbolAddress((void**)&pq_, g_pq);
    cudaGetSymbolAddress((void**)&ctx_, g_ctx);
    cudaGetSymbolAddress((void**)&proj_, g_proj);

    const int score_smem = (2 * 128 * QSTRIDE + 256 * QSTRIDE) * 2 + 128 * 132 * 4;
    cudaFuncSetAttribute(score_mma, cudaFuncAttributeMaxDynamicSharedMemorySize, score_smem);

    gemm_bf16<<<dim3(8, 8, 3), 256>>>(hs, Wq, bq, q_, Wk, bk, k_, Wv, bv, v_);
    gemm_bf16<<<dim3(8, 16, 2), 256>>>(rel, Wpk, bpk, pk_, Wpq, bpq, pq_, Wpq, bpq, pq_);
    score_mma<<<dim3(8, 8, 16), 256, score_smem>>>();
    av_mma<<<dim3(8, 16), 256>>>();
    gemm_bf16<<<dim3(8, 8, 1), 256>>>(ctx_, Wo, bo, proj_, Wo, bo, proj_, Wo, bo, proj_);
    ln_kernel<<<1024, 256>>>(hs, lng, lnb, (float*)d_out);
}